// round 3
// baseline (speedup 1.0000x reference)
#include <cuda_runtime.h>

// SSIM (8x8 box, VALID) over (32,3,512,512) fp32 -> mean(1 - ssim).
// Barrier-free version: no shared-memory row staging; each thread loads its
// 10-column window directly from global (L1 serves the overlap between
// adjacent threads). Vertical 8-row sliding sums in a register ring with
// static indices (8x unroll). One double atomicAdd per CTA.

#define FULLMASK 0xFFFFFFFFu

constexpr int W       = 512;
constexpr int OW      = 505;
constexpr int OH      = 505;
constexpr int NIMG    = 96;
constexpr int THREADS = 128;
constexpr int CPT     = 2;
constexpr int TILE_OC = THREADS * CPT; // 256
constexpr int OB      = 85;
constexpr int NB      = 6;
constexpr float C1f   = 1.0e-4f;
constexpr float C2f   = 9.0e-4f;

__device__ double g_acc;

__global__ void zero_acc_kernel() { g_acc = 0.0; }
__global__ void pad_kernel() {}
__global__ void finalize_kernel(float* out) {
    out[0] = (float)(g_acc / 24482400.0);   // 96 * 505 * 505
}

__global__ __launch_bounds__(THREADS) void ssim_kernel(
    const float* __restrict__ A, const float* __restrict__ B)
{
    __shared__ float wsum[THREADS / 32];

    const int t    = threadIdx.x;
    const int x0   = blockIdx.x * TILE_OC;
    const int band = blockIdx.y;
    const int img  = blockIdx.z;

    const int y0       = band * OB;
    const int band_out = min(OB, OH - y0);
    const int band_in  = band_out + 7;          // input rows needed

    const int gbase = x0 + CPT * t;             // first column this thread reads (even)
    // Which of the 5 float2 loads are in-bounds (cols gbase+2j, gbase+2j+1):
    const bool okj[5] = { gbase + 1 < W, gbase + 3 < W, gbase + 5 < W,
                          gbase + 7 < W, gbase + 9 < W };
    const bool fullc = okj[4];                  // all 5 loads safe (common case)

    const size_t base = (size_t)img * (size_t)(W * W) + (size_t)y0 * W + gbase;
    const float2* pa = reinterpret_cast<const float2*>(A + base);
    const float2* pb = reinterpret_cast<const float2*>(B + base);
    constexpr int ROWF2 = W / 2;                // float2 stride per row

    // Vertical sliding-window state per owned output column.
    float ring[CPT][5][8];
    float V[CPT][5];
#pragma unroll
    for (int j = 0; j < CPT; ++j)
#pragma unroll
        for (int q = 0; q < 5; ++q) {
            V[j][q] = 0.0f;
#pragma unroll
            for (int p = 0; p < 8; ++p) ring[j][q][p] = 0.0f;
        }

    float acc = 0.0f;
    const bool out_ok0 = (gbase + 0) < OW;
    const bool out_ok1 = (gbase + 1) < OW;

    const int iters = (band_in + 7) & ~7;       // 8x-unrollable trip count
    for (int ib = 0; ib < iters; ib += 8) {
#pragma unroll
        for (int p = 0; p < 8; ++p) {
            const int i = ib + p;

            // ---- load this thread's 10-col window for row i (both images) ----
            float a[10], b[10];
            if (i < band_in) {
                if (fullc) {
                    float2 u;
                    u = pa[0]; a[0] = u.x; a[1] = u.y;
                    u = pa[1]; a[2] = u.x; a[3] = u.y;
                    u = pa[2]; a[4] = u.x; a[5] = u.y;
                    u = pa[3]; a[6] = u.x; a[7] = u.y;
                    u = pa[4]; a[8] = u.x; a[9] = u.y;
                    u = pb[0]; b[0] = u.x; b[1] = u.y;
                    u = pb[1]; b[2] = u.x; b[3] = u.y;
                    u = pb[2]; b[4] = u.x; b[5] = u.y;
                    u = pb[3]; b[6] = u.x; b[7] = u.y;
                    u = pb[4]; b[8] = u.x; b[9] = u.y;
                } else {
#pragma unroll
                    for (int j5 = 0; j5 < 5; ++j5) {
                        float2 u = okj[j5] ? pa[j5] : make_float2(0.f, 0.f);
                        float2 v = okj[j5] ? pb[j5] : make_float2(0.f, 0.f);
                        a[2 * j5] = u.x; a[2 * j5 + 1] = u.y;
                        b[2 * j5] = v.x; b[2 * j5 + 1] = v.y;
                    }
                }
            } else {
#pragma unroll
                for (int k = 0; k < 10; ++k) { a[k] = 0.f; b[k] = 0.f; }
            }
            pa += ROWF2; pb += ROWF2;

            // ---- horizontal 8-sums for 2 output columns ----
            float s1 = 0.f, s2 = 0.f, s11 = 0.f, s22 = 0.f, s12 = 0.f;
#pragma unroll
            for (int k = 0; k < 8; ++k) {
                const float av = a[k], bv = b[k];
                s1  += av;              s2  += bv;
                s11 = fmaf(av, av, s11); s22 = fmaf(bv, bv, s22);
                s12 = fmaf(av, bv, s12);
            }
            float h[CPT][5];
            h[0][0] = s1; h[0][1] = s2; h[0][2] = s11; h[0][3] = s22; h[0][4] = s12;
            {
                const float a0 = a[0], b0 = b[0], a8 = a[8], b8 = b[8];
                h[1][0] = s1  - a0 + a8;
                h[1][1] = s2  - b0 + b8;
                h[1][2] = fmaf(a8, a8, s11 - a0 * a0);
                h[1][3] = fmaf(b8, b8, s22 - b0 * b0);
                h[1][4] = fmaf(a8, b8, s12 - a0 * b0);
            }

            // ---- vertical sliding update (static ring index p) ----
#pragma unroll
            for (int j = 0; j < CPT; ++j)
#pragma unroll
                for (int q = 0; q < 5; ++q) {
                    const float hv = h[j][q];
                    V[j][q] += hv - ring[j][q][p];
                    ring[j][q][p] = hv;
                }

            // ---- SSIM for completed windows ----
            if (i >= 7 && i < band_in) {
#pragma unroll
                for (int j = 0; j < CPT; ++j) {
                    if (j == 0 ? out_ok0 : out_ok1) {
                        const float mu1 = V[j][0], mu2 = V[j][1];
                        const float m11 = mu1 * mu1;
                        const float m22 = mu2 * mu2;
                        const float m12 = mu1 * mu2;
                        const float sg1  = V[j][2] - m11;
                        const float sg2  = V[j][3] - m22;
                        const float sg12 = V[j][4] - m12;
                        const float num = fmaf(2.0f, m12,  C1f) * fmaf(2.0f, sg12, C2f);
                        const float den = (m11 + m22 + C1f) * (sg1 + sg2 + C2f);
                        acc += 1.0f - __fdividef(num, den);
                    }
                }
            }
        }
    }

    // ---- reduction: warp shuffle -> smem -> one double atomic per CTA ----
#pragma unroll
    for (int o = 16; o; o >>= 1) acc += __shfl_xor_sync(FULLMASK, acc, o);
    if ((t & 31) == 0) wsum[t >> 5] = acc;
    __syncthreads();
    if (t == 0) {
        const double s = (double)wsum[0] + (double)wsum[1] +
                         (double)wsum[2] + (double)wsum[3];
        atomicAdd(&g_acc, s);
    }
}

extern "C" void kernel_launch(void* const* d_in, const int* in_sizes, int n_in,
                              void* d_out, int out_size)
{
    const float* A = (const float*)d_in[0];
    const float* B = (const float*)d_in[1];
    float* out = (float*)d_out;

    zero_acc_kernel<<<1, 1>>>();                 // 1
    pad_kernel<<<1, 1>>>();                      // 2
    pad_kernel<<<1, 1>>>();                      // 3
    dim3 grid(2, NB, NIMG);
    ssim_kernel<<<grid, THREADS>>>(A, B);        // 4  <- ncu capture position
    pad_kernel<<<1, 1>>>();                      // 5
    finalize_kernel<<<1, 1>>>(out);              // 6
}

// round 7
// speedup vs baseline: 1.7272x; 1.7272x over previous
#include <cuda_runtime.h>

// SSIM (8x8 box, VALID) over (32,3,512,512) fp32 -> mean(1 - ssim).
// Column-sum formulation: each thread owns 2 input columns, maintains 8-row
// sliding column sums (raw (a,b) ring, 32 regs). Horizontal 8-wide window
// sums are assembled across lanes with warp shuffles (even output via
// pair/quad tree, odd output incrementally). One warp per CTA = one
// 56-output-column strip; 9 strips exactly tile 505 cols -> no OOB loads.

#define FULLMASK 0xFFFFFFFFu

constexpr int W      = 512;
constexpr int OW     = 505;
constexpr int OH     = 505;
constexpr int NIMG   = 96;
constexpr int NSTRIP = 9;     // 9*56 + 1 = 505 (lane-28 even of last strip)
constexpr int NB     = 6;
constexpr int OB     = 85;
constexpr float C1f  = 1.0e-4f;
constexpr float C2f  = 9.0e-4f;

__device__ double g_part[NIMG];

__global__ void zero_acc_kernel() {
    const int i = threadIdx.x;
    if (i < NIMG) g_part[i] = 0.0;
}
__global__ void pad_kernel() {}
__global__ void finalize_kernel(float* out) {
    const int l = threadIdx.x;
    double s = 0.0;
    for (int i = l; i < NIMG; i += 32) s += g_part[i];
#pragma unroll
    for (int o = 16; o; o >>= 1) s += __shfl_xor_sync(FULLMASK, s, o);
    if (l == 0) out[0] = (float)(s / 24482400.0);   // 96 * 505 * 505
}

__global__ __launch_bounds__(32) void ssim_kernel(
    const float* __restrict__ A, const float* __restrict__ B)
{
    const int l     = threadIdx.x;
    const int strip = blockIdx.x;
    const int band  = blockIdx.y;
    const int img   = blockIdx.z;

    const int base     = strip * 56;
    const int y0       = band * OB;
    const int band_out = min(OB, OH - y0);
    const int band_in  = band_out + 7;

    const bool evenOK = (l < 28) || (strip == NSTRIP - 1 && l == 28);
    const bool oddOK  = (l < 28);

    const size_t off = (size_t)img * (size_t)(W * W) + (size_t)y0 * W + base + 2 * l;
    const float2* pa = reinterpret_cast<const float2*>(A + off);
    const float2* pb = reinterpret_cast<const float2*>(B + off);
    constexpr int ROWF2 = W / 2;

    // Raw 8-row rings for this thread's two columns.
    float ra0[8], ra1[8], rb0[8], rb1[8];
#pragma unroll
    for (int p = 0; p < 8; ++p) { ra0[p] = ra1[p] = rb0[p] = rb1[p] = 0.f; }

    // Running 8-row column sums: [col][stat] stats = a, b, aa, bb, ab
    float S[2][5];
#pragma unroll
    for (int j = 0; j < 2; ++j)
#pragma unroll
        for (int q = 0; q < 5; ++q) S[j][q] = 0.f;

    float acc = 0.f;

    // Prefetch row 0.
    float2 cura = pa[0], curb = pb[0];
    pa += ROWF2; pb += ROWF2;

    const int iters = (band_in + 7) & ~7;
    for (int ib = 0; ib < iters; ib += 8) {
#pragma unroll
        for (int p = 0; p < 8; ++p) {
            const int i = ib + p;
            if (i < band_in) {
                // ---- prefetch next row ----
                float2 nxa = cura, nxb = curb;
                if (i + 1 < band_in) {
                    nxa = pa[0]; nxb = pb[0];
                    pa += ROWF2; pb += ROWF2;
                }

                // ---- update column sums (add new row, drop row i-8) ----
                const float a0 = cura.x, a1 = cura.y;
                const float b0 = curb.x, b1 = curb.y;
                const float oa0 = ra0[p], oa1 = ra1[p];
                const float ob0 = rb0[p], ob1 = rb1[p];

                S[0][0] += a0 - oa0;              S[1][0] += a1 - oa1;
                S[0][1] += b0 - ob0;              S[1][1] += b1 - ob1;
                S[0][2] = fmaf(-oa0, oa0, fmaf(a0, a0, S[0][2]));
                S[1][2] = fmaf(-oa1, oa1, fmaf(a1, a1, S[1][2]));
                S[0][3] = fmaf(-ob0, ob0, fmaf(b0, b0, S[0][3]));
                S[1][3] = fmaf(-ob1, ob1, fmaf(b1, b1, S[1][3]));
                S[0][4] = fmaf(-oa0, ob0, fmaf(a0, b0, S[0][4]));
                S[1][4] = fmaf(-oa1, ob1, fmaf(a1, b1, S[1][4]));

                ra0[p] = a0; ra1[p] = a1; rb0[p] = b0; rb1[p] = b1;

                // ---- horizontal window sums across lanes + SSIM ----
                if (i >= 7) {
                    float Ev[5], Od[5];
#pragma unroll
                    for (int q = 0; q < 5; ++q) {
                        const float s0 = S[0][q], s1 = S[1][q];
                        const float P = s0 + s1;
                        const float Q = P + __shfl_down_sync(FULLMASK, P, 1);
                        const float E = Q + __shfl_down_sync(FULLMASK, Q, 2);
                        const float O = (E - s0) + __shfl_down_sync(FULLMASK, s0, 4);
                        Ev[q] = E; Od[q] = O;
                    }
                    {   // even output (x = base + 2l)
                        const float mu1 = Ev[0], mu2 = Ev[1];
                        const float m11 = mu1 * mu1, m22 = mu2 * mu2, m12 = mu1 * mu2;
                        const float sg1 = Ev[2] - m11, sg2 = Ev[3] - m22, sg12 = Ev[4] - m12;
                        const float num = fmaf(2.f, m12, C1f) * fmaf(2.f, sg12, C2f);
                        const float den = (m11 + m22 + C1f) * (sg1 + sg2 + C2f);
                        const float v = 1.f - __fdividef(num, den);
                        acc += evenOK ? v : 0.f;
                    }
                    {   // odd output (x = base + 2l + 1)
                        const float mu1 = Od[0], mu2 = Od[1];
                        const float m11 = mu1 * mu1, m22 = mu2 * mu2, m12 = mu1 * mu2;
                        const float sg1 = Od[2] - m11, sg2 = Od[3] - m22, sg12 = Od[4] - m12;
                        const float num = fmaf(2.f, m12, C1f) * fmaf(2.f, sg12, C2f);
                        const float den = (m11 + m22 + C1f) * (sg1 + sg2 + C2f);
                        const float v = 1.f - __fdividef(num, den);
                        acc += oddOK ? v : 0.f;
                    }
                }
                cura = nxa; curb = nxb;
            }
        }
    }

    // ---- warp reduction, one double atomic per warp into per-image slot ----
#pragma unroll
    for (int o = 16; o; o >>= 1) acc += __shfl_xor_sync(FULLMASK, acc, o);
    if (l == 0) atomicAdd(&g_part[img], (double)acc);
}

extern "C" void kernel_launch(void* const* d_in, const int* in_sizes, int n_in,
                              void* d_out, int out_size)
{
    const float* A = (const float*)d_in[0];
    const float* B = (const float*)d_in[1];
    float* out = (float*)d_out;

    zero_acc_kernel<<<1, 128>>>();               // 1
    pad_kernel<<<1, 1>>>();                      // 2
    pad_kernel<<<1, 1>>>();                      // 3
    dim3 grid(NSTRIP, NB, NIMG);                 // 9 x 6 x 96 = 5184 warps
    ssim_kernel<<<grid, 32>>>(A, B);             // 4  <- ncu capture position
    pad_kernel<<<1, 1>>>();                      // 5
    finalize_kernel<<<1, 32>>>(out);             // 6
}

// round 9
// speedup vs baseline: 2.0508x; 1.1873x over previous
#include <cuda_runtime.h>

// SSIM (8x8 box, VALID) over (32,3,512,512) fp32 -> mean(1 - ssim).
// Column-sum formulation, warp-per-strip. R8: single-wave grid (NB=4 so
// 3456 warp-CTAs fit in one wave at ~26-29 warps/SM) + 2-row-deep global
// load pipeline to cover DRAM latency.

#define FULLMASK 0xFFFFFFFFu

constexpr int W      = 512;
constexpr int OW     = 505;
constexpr int OH     = 505;
constexpr int NIMG   = 96;
constexpr int NSTRIP = 9;     // 9*56 + 1 = 505 (lane-28 even of last strip)
constexpr int NB     = 4;
constexpr int OB     = 127;   // 4*127 = 508 >= 505
constexpr float C1f  = 1.0e-4f;
constexpr float C2f  = 9.0e-4f;

__device__ double g_part[NIMG];

__global__ void zero_acc_kernel() {
    const int i = threadIdx.x;
    if (i < NIMG) g_part[i] = 0.0;
}
__global__ void pad_kernel() {}
__global__ void finalize_kernel(float* out) {
    const int l = threadIdx.x;
    double s = 0.0;
    for (int i = l; i < NIMG; i += 32) s += g_part[i];
#pragma unroll
    for (int o = 16; o; o >>= 1) s += __shfl_xor_sync(FULLMASK, s, o);
    if (l == 0) out[0] = (float)(s / 24482400.0);   // 96 * 505 * 505
}

__global__ __launch_bounds__(32) void ssim_kernel(
    const float* __restrict__ A, const float* __restrict__ B)
{
    const int l     = threadIdx.x;
    const int strip = blockIdx.x;
    const int band  = blockIdx.y;
    const int img   = blockIdx.z;

    const int base     = strip * 56;
    const int y0       = band * OB;
    const int band_out = min(OB, OH - y0);
    const int band_in  = band_out + 7;

    const bool evenOK = (l < 28) || (strip == NSTRIP - 1 && l == 28);
    const bool oddOK  = (l < 28);

    const size_t off = (size_t)img * (size_t)(W * W) + (size_t)y0 * W + base + 2 * l;
    const float2* pa = reinterpret_cast<const float2*>(A + off);
    const float2* pb = reinterpret_cast<const float2*>(B + off);
    constexpr int ROWF2 = W / 2;

    // Raw 8-row rings for this thread's two columns.
    float ra0[8], ra1[8], rb0[8], rb1[8];
#pragma unroll
    for (int p = 0; p < 8; ++p) { ra0[p] = ra1[p] = rb0[p] = rb1[p] = 0.f; }

    // Running 8-row column sums: [col][stat] stats = a, b, aa, bb, ab
    float S[2][5];
#pragma unroll
    for (int j = 0; j < 2; ++j)
#pragma unroll
        for (int q = 0; q < 5; ++q) S[j][q] = 0.f;

    float acc = 0.f;

    // 2-deep load pipeline: cur = row i, nx1 = row i+1 (in flight/arrived).
    float2 cura = pa[0], curb = pb[0];
    float2 nx1a = make_float2(0.f, 0.f), nx1b = nx1a;
    if (1 < band_in) { nx1a = pa[ROWF2]; nx1b = pb[ROWF2]; }
    pa += 2 * ROWF2; pb += 2 * ROWF2;

    const int iters = (band_in + 7) & ~7;
    for (int ib = 0; ib < iters; ib += 8) {
#pragma unroll
        for (int p = 0; p < 8; ++p) {
            const int i = ib + p;
            if (i < band_in) {
                // ---- issue load for row i+2 (two iterations of cover) ----
                float2 nx2a = make_float2(0.f, 0.f), nx2b = nx2a;
                if (i + 2 < band_in) {
                    nx2a = pa[0]; nx2b = pb[0];
                    pa += ROWF2; pb += ROWF2;
                }

                // ---- update column sums (add row i, drop row i-8) ----
                const float a0 = cura.x, a1 = cura.y;
                const float b0 = curb.x, b1 = curb.y;
                const float oa0 = ra0[p], oa1 = ra1[p];
                const float ob0 = rb0[p], ob1 = rb1[p];

                S[0][0] += a0 - oa0;              S[1][0] += a1 - oa1;
                S[0][1] += b0 - ob0;              S[1][1] += b1 - ob1;
                S[0][2] = fmaf(-oa0, oa0, fmaf(a0, a0, S[0][2]));
                S[1][2] = fmaf(-oa1, oa1, fmaf(a1, a1, S[1][2]));
                S[0][3] = fmaf(-ob0, ob0, fmaf(b0, b0, S[0][3]));
                S[1][3] = fmaf(-ob1, ob1, fmaf(b1, b1, S[1][3]));
                S[0][4] = fmaf(-oa0, ob0, fmaf(a0, b0, S[0][4]));
                S[1][4] = fmaf(-oa1, ob1, fmaf(a1, b1, S[1][4]));

                ra0[p] = a0; ra1[p] = a1; rb0[p] = b0; rb1[p] = b1;

                // ---- horizontal window sums across lanes + SSIM ----
                if (i >= 7) {
                    float Ev[5], Od[5];
#pragma unroll
                    for (int q = 0; q < 5; ++q) {
                        const float s0 = S[0][q], s1 = S[1][q];
                        const float P = s0 + s1;
                        const float Q = P + __shfl_down_sync(FULLMASK, P, 1);
                        const float E = Q + __shfl_down_sync(FULLMASK, Q, 2);
                        const float O = (E - s0) + __shfl_down_sync(FULLMASK, s0, 4);
                        Ev[q] = E; Od[q] = O;
                    }
                    {   // even output (x = base + 2l)
                        const float mu1 = Ev[0], mu2 = Ev[1];
                        const float m11 = mu1 * mu1, m22 = mu2 * mu2, m12 = mu1 * mu2;
                        const float sg1 = Ev[2] - m11, sg2 = Ev[3] - m22, sg12 = Ev[4] - m12;
                        const float num = fmaf(2.f, m12, C1f) * fmaf(2.f, sg12, C2f);
                        const float den = (m11 + m22 + C1f) * (sg1 + sg2 + C2f);
                        const float v = 1.f - __fdividef(num, den);
                        acc += evenOK ? v : 0.f;
                    }
                    {   // odd output (x = base + 2l + 1)
                        const float mu1 = Od[0], mu2 = Od[1];
                        const float m11 = mu1 * mu1, m22 = mu2 * mu2, m12 = mu1 * mu2;
                        const float sg1 = Od[2] - m11, sg2 = Od[3] - m22, sg12 = Od[4] - m12;
                        const float num = fmaf(2.f, m12, C1f) * fmaf(2.f, sg12, C2f);
                        const float den = (m11 + m22 + C1f) * (sg1 + sg2 + C2f);
                        const float v = 1.f - __fdividef(num, den);
                        acc += oddOK ? v : 0.f;
                    }
                }
                cura = nx1a; curb = nx1b;
                nx1a = nx2a; nx1b = nx2b;
            }
        }
    }

    // ---- warp reduction, one double atomic per warp into per-image slot ----
#pragma unroll
    for (int o = 16; o; o >>= 1) acc += __shfl_xor_sync(FULLMASK, acc, o);
    if (l == 0) atomicAdd(&g_part[img], (double)acc);
}

extern "C" void kernel_launch(void* const* d_in, const int* in_sizes, int n_in,
                              void* d_out, int out_size)
{
    const float* A = (const float*)d_in[0];
    const float* B = (const float*)d_in[1];
    float* out = (float*)d_out;

    zero_acc_kernel<<<1, 128>>>();               // 1
    pad_kernel<<<1, 1>>>();                      // 2
    pad_kernel<<<1, 1>>>();                      // 3
    dim3 grid(NSTRIP, NB, NIMG);                 // 9 x 4 x 96 = 3456 warps (1 wave)
    ssim_kernel<<<grid, 32>>>(A, B);             // 4  <- ncu capture position
    pad_kernel<<<1, 1>>>();                      // 5
    finalize_kernel<<<1, 32>>>(out);             // 6
}

// round 10
// speedup vs baseline: 2.1253x; 1.0363x over previous
#include <cuda_runtime.h>

// SSIM (8x8 box, VALID) over (32,3,512,512) fp32 -> mean(1 - ssim).
// Column-sum formulation, warp-per-strip. R10: NB=5 bands of OB=101
// (505 exactly, no partial band; 108 rows/warp) and launch_bounds(32,30)
// (regs<=68) so the 4320-CTA grid runs as one full wave at ~30 warps/SM.

#define FULLMASK 0xFFFFFFFFu

constexpr int W      = 512;
constexpr int OW     = 505;
constexpr int OH     = 505;
constexpr int NIMG   = 96;
constexpr int NSTRIP = 9;     // 9*56 + 1 = 505 (lane-28 even of last strip)
constexpr int NB     = 5;
constexpr int OB     = 101;   // 5*101 = 505 exactly
constexpr float C1f  = 1.0e-4f;
constexpr float C2f  = 9.0e-4f;

__device__ double g_part[NIMG];

__global__ void zero_acc_kernel() {
    const int i = threadIdx.x;
    if (i < NIMG) g_part[i] = 0.0;
}
__global__ void pad_kernel() {}
__global__ void finalize_kernel(float* out) {
    const int l = threadIdx.x;
    double s = 0.0;
    for (int i = l; i < NIMG; i += 32) s += g_part[i];
#pragma unroll
    for (int o = 16; o; o >>= 1) s += __shfl_xor_sync(FULLMASK, s, o);
    if (l == 0) out[0] = (float)(s / 24482400.0);   // 96 * 505 * 505
}

__global__ __launch_bounds__(32, 30) void ssim_kernel(
    const float* __restrict__ A, const float* __restrict__ B)
{
    const int l     = threadIdx.x;
    const int strip = blockIdx.x;
    const int band  = blockIdx.y;
    const int img   = blockIdx.z;

    const int base = strip * 56;
    const int y0   = band * OB;
    constexpr int band_out = OB;        // every band is full (5*101 = 505)
    constexpr int band_in  = band_out + 7;   // 108

    const bool evenOK = (l < 28) || (strip == NSTRIP - 1 && l == 28);
    const bool oddOK  = (l < 28);

    const size_t off = (size_t)img * (size_t)(W * W) + (size_t)y0 * W + base + 2 * l;
    const float2* pa = reinterpret_cast<const float2*>(A + off);
    const float2* pb = reinterpret_cast<const float2*>(B + off);
    constexpr int ROWF2 = W / 2;

    // Raw 8-row rings for this thread's two columns.
    float ra0[8], ra1[8], rb0[8], rb1[8];
#pragma unroll
    for (int p = 0; p < 8; ++p) { ra0[p] = ra1[p] = rb0[p] = rb1[p] = 0.f; }

    // Running 8-row column sums: [col][stat] stats = a, b, aa, bb, ab
    float S[2][5];
#pragma unroll
    for (int j = 0; j < 2; ++j)
#pragma unroll
        for (int q = 0; q < 5; ++q) S[j][q] = 0.f;

    float acc = 0.f;

    // 2-deep load pipeline: cur = row i, nx1 = row i+1 (in flight/arrived).
    float2 cura = pa[0], curb = pb[0];
    float2 nx1a = pa[ROWF2], nx1b = pb[ROWF2];
    pa += 2 * ROWF2; pb += 2 * ROWF2;

    constexpr int iters = (band_in + 7) & ~7;   // 112
    for (int ib = 0; ib < iters; ib += 8) {
#pragma unroll
        for (int p = 0; p < 8; ++p) {
            const int i = ib + p;
            if (i < band_in) {
                // ---- issue load for row i+2 (two iterations of cover) ----
                float2 nx2a = make_float2(0.f, 0.f), nx2b = nx2a;
                if (i + 2 < band_in) {
                    nx2a = pa[0]; nx2b = pb[0];
                    pa += ROWF2; pb += ROWF2;
                }

                // ---- update column sums (add row i, drop row i-8) ----
                const float a0 = cura.x, a1 = cura.y;
                const float b0 = curb.x, b1 = curb.y;
                const float oa0 = ra0[p], oa1 = ra1[p];
                const float ob0 = rb0[p], ob1 = rb1[p];

                S[0][0] += a0 - oa0;              S[1][0] += a1 - oa1;
                S[0][1] += b0 - ob0;              S[1][1] += b1 - ob1;
                S[0][2] = fmaf(-oa0, oa0, fmaf(a0, a0, S[0][2]));
                S[1][2] = fmaf(-oa1, oa1, fmaf(a1, a1, S[1][2]));
                S[0][3] = fmaf(-ob0, ob0, fmaf(b0, b0, S[0][3]));
                S[1][3] = fmaf(-ob1, ob1, fmaf(b1, b1, S[1][3]));
                S[0][4] = fmaf(-oa0, ob0, fmaf(a0, b0, S[0][4]));
                S[1][4] = fmaf(-oa1, ob1, fmaf(a1, b1, S[1][4]));

                ra0[p] = a0; ra1[p] = a1; rb0[p] = b0; rb1[p] = b1;

                // ---- horizontal window sums across lanes + SSIM ----
                if (i >= 7) {
                    float Ev[5], Od[5];
#pragma unroll
                    for (int q = 0; q < 5; ++q) {
                        const float s0 = S[0][q], s1 = S[1][q];
                        const float P = s0 + s1;
                        const float Q = P + __shfl_down_sync(FULLMASK, P, 1);
                        const float E = Q + __shfl_down_sync(FULLMASK, Q, 2);
                        const float O = (E - s0) + __shfl_down_sync(FULLMASK, s0, 4);
                        Ev[q] = E; Od[q] = O;
                    }
                    {   // even output (x = base + 2l)
                        const float mu1 = Ev[0], mu2 = Ev[1];
                        const float m11 = mu1 * mu1, m22 = mu2 * mu2, m12 = mu1 * mu2;
                        const float sg1 = Ev[2] - m11, sg2 = Ev[3] - m22, sg12 = Ev[4] - m12;
                        const float num = fmaf(2.f, m12, C1f) * fmaf(2.f, sg12, C2f);
                        const float den = (m11 + m22 + C1f) * (sg1 + sg2 + C2f);
                        const float v = 1.f - __fdividef(num, den);
                        acc += evenOK ? v : 0.f;
                    }
                    {   // odd output (x = base + 2l + 1)
                        const float mu1 = Od[0], mu2 = Od[1];
                        const float m11 = mu1 * mu1, m22 = mu2 * mu2, m12 = mu1 * mu2;
                        const float sg1 = Od[2] - m11, sg2 = Od[3] - m22, sg12 = Od[4] - m12;
                        const float num = fmaf(2.f, m12, C1f) * fmaf(2.f, sg12, C2f);
                        const float den = (m11 + m22 + C1f) * (sg1 + sg2 + C2f);
                        const float v = 1.f - __fdividef(num, den);
                        acc += oddOK ? v : 0.f;
                    }
                }
                cura = nx1a; curb = nx1b;
                nx1a = nx2a; nx1b = nx2b;
            }
        }
    }

    // ---- warp reduction, one double atomic per warp into per-image slot ----
#pragma unroll
    for (int o = 16; o; o >>= 1) acc += __shfl_xor_sync(FULLMASK, acc, o);
    if (l == 0) atomicAdd(&g_part[img], (double)acc);
}

extern "C" void kernel_launch(void* const* d_in, const int* in_sizes, int n_in,
                              void* d_out, int out_size)
{
    const float* A = (const float*)d_in[0];
    const float* B = (const float*)d_in[1];
    float* out = (float*)d_out;

    zero_acc_kernel<<<1, 128>>>();               // 1
    pad_kernel<<<1, 1>>>();                      // 2
    pad_kernel<<<1, 1>>>();                      // 3
    dim3 grid(NSTRIP, NB, NIMG);                 // 9 x 5 x 96 = 4320 warps (1 wave @30/SM)
    ssim_kernel<<<grid, 32>>>(A, B);             // 4  <- ncu capture position
    pad_kernel<<<1, 1>>>();                      // 5
    finalize_kernel<<<1, 32>>>(out);             // 6
}